// round 14
// baseline (speedup 1.0000x reference)
#include <cuda_runtime.h>
#include <cuda_fp16.h>
#include <math.h>
#include <stdint.h>

#define BATCH 256
#define C1 256
#define IMGD 28
#define NPRIM 1152
#define NC 10
#define PCD 8
#define DCD 16
#define KTOT 20736           // 81 r * 256 ic  (k = r*256 + ic)
#define MTOT 9216            // 256 b * 36 sp
#define NKT (KTOT / 64)      // 324

// ---------------- scratch ----------------
__device__ __align__(16) __half g_xh[(size_t)BATCH * 400 * C1];  // conv1 out fp16 [b][px][ic]
__device__ __align__(16) __half g_Bh[(size_t)C1 * KTOT];         // pc_w fp16 [oc][k]
__device__ __align__(16) __half g_c1w[256 * 128];                // conv1_w fp16 [oc][k pad 128]
__device__ float g_pc[(size_t)MTOT * C1];                        // pc conv out [m][oc]
__device__ float g_u[BATCH * NPRIM * PCD];                       // squashed, [n][b][p]
__device__ __align__(16) __half g_WUh[(size_t)BATCH * NPRIM * NC * DCD];  // u_hat fp16
__device__ float g_v[BATCH * NC * DCD];
__device__ __align__(16) __half g_w2h[512 * 1024];
__device__ __align__(16) __half g_w3h[1024 * 784];

__device__ __forceinline__ uint32_t smem_u32(const void* p) {
    uint32_t a;
    asm("{ .reg .u64 t; cvta.to.shared.u64 t, %1; cvt.u32.u64 %0, t; }" : "=r"(a) : "l"(p));
    return a;
}
#define CP_ASYNC16(sa, ga) \
    asm volatile("cp.async.cg.shared.global [%0], [%1], 16;" :: "r"(sa), "l"(ga))
#define CP_COMMIT() asm volatile("cp.async.commit_group;" ::: "memory")
#define CP_WAIT2()  asm volatile("cp.async.wait_group 2;" ::: "memory")
#define CP_WAIT0()  asm volatile("cp.async.wait_group 0;" ::: "memory")
#define LDMX4(r0, r1, r2, r3, a) \
    asm volatile("ldmatrix.sync.aligned.m8n8.x4.shared.b16 {%0,%1,%2,%3}, [%4];" \
        : "=r"(r0), "=r"(r1), "=r"(r2), "=r"(r3) : "r"(a))
#define MMAF16(c, a, b0, b1) \
    asm volatile("mma.sync.aligned.m16n8k16.row.col.f32.f16.f16.f32 " \
        "{%0,%1,%2,%3},{%4,%5,%6,%7},{%8,%9},{%0,%1,%2,%3};" \
        : "+f"((c)[0]), "+f"((c)[1]), "+f"((c)[2]), "+f"((c)[3]) \
        : "r"((a)[0]), "r"((a)[1]), "r"((a)[2]), "r"((a)[3]), "r"(b0), "r"(b1))

// ---------------- conv1_w -> fp16, [oc][128] zero-padded ----------------
__global__ void convert_c1w_kernel(const float* __restrict__ w) {
    const int oc = blockIdx.x, k = threadIdx.x;
    g_c1w[oc * 128 + k] = (k < 81) ? __float2half_rn(w[oc * 81 + k]) : __half(0);
}

// ---------------- pc_w -> fp16 transposed per-oc (coalesced both sides) ----------------
__global__ void convert_w_kernel(const float* __restrict__ w) {
    __shared__ __half sw[KTOT];
    const int oc = blockIdx.x, t = threadIdx.x;   // 256 threads
    const float* src = w + (size_t)oc * KTOT;
    for (int i = t; i < KTOT; i += 256) sw[i] = __float2half_rn(src[i]);
    __syncthreads();
    __half* dst = g_Bh + (size_t)oc * KTOT;
    for (int r = 0; r < 81; ++r) dst[r * 256 + t] = sw[t * 81 + r];
}

// ---------------- decoder w2/w3 -> fp16 ----------------
__global__ void convert_dec_kernel(const float* __restrict__ w2,
                                   const float* __restrict__ w3) {
    const int i = blockIdx.x * 256 + threadIdx.x;
    if (i < 512 * 1024) g_w2h[i] = __float2half_rn(w2[i]);
    if (i < 1024 * 784) g_w3h[i] = __float2half_rn(w3[i]);
}

// ---------------- conv1 as implicit GEMM: M=102400, N=256, K=81->128 ----------------
#define C1_SMEM (8192 + 65536)

__global__ void __launch_bounds__(512, 2) conv1_gemm_kernel(const float* __restrict__ in,
                                                            const float* __restrict__ bias) {
    extern __shared__ char sm[];
    float* s_bias = (float*)sm;
    float* s_img = (float*)(sm + 1024);
    const uint32_t smb = smem_u32(sm);
    const int tid = threadIdx.x, lane = tid & 31, wid = tid >> 5;
    const int mtile = blockIdx.x, ntile = blockIdx.y;
    if (tid < 128) s_bias[tid] = bias[ntile * 128 + tid];

    const int m0 = mtile * 128;
    const int b0 = m0 / 400;
    const int b1 = (b0 + 1 < BATCH) ? b0 + 1 : b0;

    #pragma unroll
    for (int i = 0; i < 4; ++i) {
        const int lin = tid + i * 512;
        const int row = lin >> 4, c16 = lin & 15;
        const int kc = c16 >> 3, ch = c16 & 7;
        const uint32_t dst = smb + 8192 + kc * 32768 + 16384
                           + row * 128 + ((ch ^ (row & 7)) << 4);
        const size_t src = (size_t)(ntile * 128 + row) * 256 + kc * 128 + ch * 16;
        CP_ASYNC16(dst, (const char*)g_c1w + src);
    }
    CP_COMMIT();

    for (int i = tid; i < 2 * 784; i += 512) {
        const int im = (i >= 784);
        s_img[i] = in[(im ? b1 : b0) * 784 + (i - im * 784)];
    }
    __syncthreads();

    {
        const int row = tid >> 2;
        const int cb = (tid & 3) * 32;
        const int m = m0 + row;
        const int bb = m / 400, px = m - bb * 400;
        const int ibase = ((bb == b0) ? 0 : 784) + (px / 20) * 28 + (px % 20);
        #pragma unroll
        for (int p = 0; p < 16; ++p) {
            const int k0 = cb + 2 * p;
            float v0 = 0.f, v1 = 0.f;
            if (k0 < 81) {
                int ky = (k0 * 57) >> 9, kx = k0 - ky * 9;
                v0 = s_img[ibase + ky * 28 + kx];
            }
            if (k0 + 1 < 81) {
                int ky = ((k0 + 1) * 57) >> 9, kx = k0 + 1 - ky * 9;
                v1 = s_img[ibase + ky * 28 + kx];
            }
            const int within = k0 & 63;
            const int off = 8192 + (k0 >> 6) * 32768 + row * 128
                          + (((within >> 3) ^ (row & 7)) << 4) + (within & 7) * 2;
            *(__half2*)(sm + off) = __floats2half2_rn(v0, v1);
        }
    }
    CP_WAIT0();
    __syncthreads();

    const int warp_m = wid >> 2, warp_n = wid & 3;
    int a_off[2], a_sw[2];
    #pragma unroll
    for (int sub = 0; sub < 2; ++sub) {
        int row = warp_m * 32 + sub * 16 + (lane & 15);
        a_off[sub] = row * 128; a_sw[sub] = row & 7;
    }
    const int a_cb = lane >> 4;
    int b_off[2], b_sw[2];
    #pragma unroll
    for (int j = 0; j < 2; ++j) {
        int row = warp_n * 32 + j * 16 + ((lane >> 4) << 3) + (lane & 7);
        b_off[j] = row * 128; b_sw[j] = row & 7;
    }
    const int b_cb = (lane >> 3) & 1;

    float acc[2][4][4];
    #pragma unroll
    for (int m = 0; m < 2; ++m)
        #pragma unroll
        for (int j = 0; j < 4; ++j)
            #pragma unroll
            for (int q = 0; q < 4; ++q) acc[m][j][q] = 0.f;

    #pragma unroll
    for (int t = 0; t < 2; ++t) {
        const uint32_t sA = smb + 8192 + t * 32768;
        const uint32_t sB = sA + 16384;
        #pragma unroll
        for (int ks = 0; ks < 4; ++ks) {
            uint32_t a[2][4], bfr[2][4];
            #pragma unroll
            for (int sub = 0; sub < 2; ++sub) {
                uint32_t co = ((((ks << 1) + a_cb) ^ a_sw[sub]) << 4);
                LDMX4(a[sub][0], a[sub][1], a[sub][2], a[sub][3], sA + a_off[sub] + co);
            }
            #pragma unroll
            for (int j = 0; j < 2; ++j) {
                uint32_t co = ((((ks << 1) + b_cb) ^ b_sw[j]) << 4);
                LDMX4(bfr[j][0], bfr[j][1], bfr[j][2], bfr[j][3], sB + b_off[j] + co);
            }
            #pragma unroll
            for (int msub = 0; msub < 2; ++msub)
                #pragma unroll
                for (int j = 0; j < 2; ++j) {
                    MMAF16(acc[msub][2 * j],     a[msub], bfr[j][0], bfr[j][1]);
                    MMAF16(acc[msub][2 * j + 1], a[msub], bfr[j][2], bfr[j][3]);
                }
        }
    }

    const int r = lane >> 2, cpair = (lane & 3) * 2;
    #pragma unroll
    for (int msub = 0; msub < 2; ++msub) {
        const int gm0 = m0 + warp_m * 32 + msub * 16 + r;
        #pragma unroll
        for (int j = 0; j < 4; ++j) {
            const int ln = warp_n * 32 + j * 8 + cpair;
            const int gn = ntile * 128 + ln;
            const float bb0 = s_bias[ln], bb1 = s_bias[ln + 1];
            __half2 v0 = __floats2half2_rn(fmaxf(acc[msub][j][0] + bb0, 0.f),
                                           fmaxf(acc[msub][j][1] + bb1, 0.f));
            __half2 v1 = __floats2half2_rn(fmaxf(acc[msub][j][2] + bb0, 0.f),
                                           fmaxf(acc[msub][j][3] + bb1, 0.f));
            *(__half2*)&g_xh[(size_t)gm0 * C1 + gn] = v0;
            *(__half2*)&g_xh[(size_t)(gm0 + 8) * C1 + gn] = v1;
        }
    }
}

// ---------------- implicit fp16 GEMM: 64x128 tile, 256 threads, 2 CTA/SM, 4-stage ----------------
#define STG 24576
#define GEMM_SMEM (1024 + 4 * STG)

__global__ void __launch_bounds__(256, 2) gemm_kernel(const float* __restrict__ bias) {
    extern __shared__ char sm[];
    float* s_bias = (float*)sm;
    const uint32_t smb = smem_u32(sm);
    const int tid = threadIdx.x, lane = tid & 31, wid = tid >> 5;
    const int mtile = blockIdx.x, ntile = blockIdx.y;
    if (tid < 128) s_bias[tid] = bias[ntile * 128 + tid];

    const char* Bh = (const char*)g_Bh + (size_t)ntile * 128 * (KTOT * 2);

    int abase[2], aso2[2];
    #pragma unroll
    for (int i = 0; i < 2; ++i) {
        const int lin = tid + i * 256;
        const int ar = lin >> 3, ch = lin & 7;
        const int m = mtile * 64 + ar;
        const int bb = m / 36, sp = m - bb * 36;
        const int pbase = (2 * (sp / 6)) * 20 + 2 * (sp % 6);
        abase[i] = ((bb * 400 + pbase) << 8) + ch * 8;
        aso2[i] = ar * 128 + ((ch ^ (ar & 7)) << 4);
    }
    int brow[4], bso[4], bch[4];
    #pragma unroll
    for (int i = 0; i < 4; ++i) {
        int lin = tid + i * 256;
        brow[i] = lin >> 3; bch[i] = lin & 7;
        bso[i] = brow[i] * 128 + ((bch[i] ^ (brow[i] & 7)) << 4);
    }

    const int warp_m = wid >> 2, warp_n = wid & 3;
    int a_off[2], a_sw[2];
    #pragma unroll
    for (int sub = 0; sub < 2; ++sub) {
        int row = warp_m * 32 + sub * 16 + (lane & 15);
        a_off[sub] = row * 128; a_sw[sub] = row & 7;
    }
    const int a_cb = lane >> 4;
    int b_off[2], b_sw[2];
    #pragma unroll
    for (int j = 0; j < 2; ++j) {
        int row = warp_n * 32 + j * 16 + ((lane >> 4) << 3) + (lane & 7);
        b_off[j] = row * 128; b_sw[j] = row & 7;
    }
    const int b_cb = (lane >> 3) & 1;

    float acc[2][4][4];
    #pragma unroll
    for (int m = 0; m < 2; ++m)
        #pragma unroll
        for (int j = 0; j < 4; ++j)
            #pragma unroll
            for (int q = 0; q < 4; ++q) acc[m][j][q] = 0.f;

    auto issue = [&](int kk, int buf) {
        const uint32_t sA = smb + 1024 + buf * STG;
        const uint32_t sB = sA + 8192;
        const int r = kk >> 2, icq = kk & 3;
        const int dy = (r * 57) >> 9;
        const int poff = ((dy * 20 + (r - dy * 9)) << 8) + (icq << 6);
        #pragma unroll
        for (int i = 0; i < 2; ++i) {
            const size_t e = (size_t)(abase[i] + poff) * 2;
            CP_ASYNC16(sA + aso2[i], (const char*)g_xh + e);
        }
        const size_t kbyte = (size_t)kk * 128;
        #pragma unroll
        for (int i = 0; i < 4; ++i) {
            const size_t go = (size_t)brow[i] * (KTOT * 2) + kbyte + bch[i] * 16;
            CP_ASYNC16(sB + bso[i], Bh + go);
        }
        CP_COMMIT();
    };

    issue(0, 0); issue(1, 1); issue(2, 2);

    for (int t = 0; t < NKT; ++t) {
        CP_WAIT2();
        __syncthreads();
        if (t + 3 < NKT) issue(t + 3, (t + 3) & 3);
        else CP_COMMIT();
        const uint32_t sA = smb + 1024 + (t & 3) * STG;
        const uint32_t sB = sA + 8192;
        #pragma unroll
        for (int ks = 0; ks < 4; ++ks) {
            uint32_t a[2][4], bfr[2][4];
            #pragma unroll
            for (int sub = 0; sub < 2; ++sub) {
                uint32_t co = ((((ks << 1) + a_cb) ^ a_sw[sub]) << 4);
                LDMX4(a[sub][0], a[sub][1], a[sub][2], a[sub][3], sA + a_off[sub] + co);
            }
            #pragma unroll
            for (int j = 0; j < 2; ++j) {
                uint32_t co = ((((ks << 1) + b_cb) ^ b_sw[j]) << 4);
                LDMX4(bfr[j][0], bfr[j][1], bfr[j][2], bfr[j][3], sB + b_off[j] + co);
            }
            #pragma unroll
            for (int msub = 0; msub < 2; ++msub)
                #pragma unroll
                for (int j = 0; j < 2; ++j) {
                    MMAF16(acc[msub][2 * j],     a[msub], bfr[j][0], bfr[j][1]);
                    MMAF16(acc[msub][2 * j + 1], a[msub], bfr[j][2], bfr[j][3]);
                }
        }
    }
    CP_WAIT0();

    const int r = lane >> 2, cpair = (lane & 3) * 2;
    #pragma unroll
    for (int msub = 0; msub < 2; ++msub) {
        const int gm0 = mtile * 64 + warp_m * 32 + msub * 16 + r;
        #pragma unroll
        for (int j = 0; j < 4; ++j) {
            const int ln = warp_n * 32 + j * 8 + cpair;
            const int gn = ntile * 128 + ln;
            const float b0 = s_bias[ln], b1 = s_bias[ln + 1];
            float2 v0 = {acc[msub][j][0] + b0, acc[msub][j][1] + b1};
            float2 v1 = {acc[msub][j][2] + b0, acc[msub][j][3] + b1};
            *(float2*)&g_pc[(size_t)gm0 * C1 + gn] = v0;
            *(float2*)&g_pc[(size_t)(gm0 + 8) * C1 + gn] = v1;
        }
    }
}

// ---------------- squash ----------------
__global__ void squash_u_kernel() {
    __shared__ float s[8][256];
    const int tid = threadIdx.x, w = tid >> 5, l = tid & 31;
    const int m = blockIdx.x * 8 + w;
    const float* row = g_pc + (size_t)m * C1;
    float4 r0 = ((const float4*)row)[l * 2];
    float4 r1 = ((const float4*)row)[l * 2 + 1];
    *(float4*)&s[w][l * 8]     = r0;
    *(float4*)&s[w][l * 8 + 4] = r1;
    __syncwarp();
    float v[PCD];
    float sq = 0.f;
    #pragma unroll
    for (int d = 0; d < PCD; ++d) {
        v[d] = s[w][d * 32 + l];
        sq += v[d] * v[d];
    }
    const float sc = sq / (1.f + sq) / sqrtf(sq + 1e-7f);
    const int b = m / 36, sp = m % 36;
    const int n = l * 36 + sp;
    float4 o0 = {v[0] * sc, v[1] * sc, v[2] * sc, v[3] * sc};
    float4 o1 = {v[4] * sc, v[5] * sc, v[6] * sc, v[7] * sc};
    float* dst = g_u + ((size_t)n * BATCH + b) * PCD;
    *(float4*)dst = o0;
    *(float4*)(dst + 4) = o1;
}

// ---------------- u_hat -> fp16 ----------------
__global__ void wu_kernel(const float* __restrict__ W) {
    __shared__ float s_u[64 * PCD];
    const int n = blockIdx.x;
    const int t = threadIdx.x;
    float wr[PCD];
    #pragma unroll
    for (int p = 0; p < PCD; ++p) wr[p] = W[n * (NC * DCD * PCD) + t * PCD + p];
    for (int b0 = 0; b0 < BATCH; b0 += 64) {
        __syncthreads();
        const uint4* src = (const uint4*)(g_u + ((size_t)n * BATCH + b0) * PCD);
        for (int i = t; i < 128; i += 160) ((uint4*)s_u)[i] = src[i];
        __syncthreads();
        for (int bb = 0; bb < 64; ++bb) {
            const float* up = &s_u[bb * PCD];
            float dot = 0.f;
            #pragma unroll
            for (int p = 0; p < PCD; ++p) dot += wr[p] * up[p];
            g_WUh[((size_t)((b0 + bb) * NPRIM + n)) * 160 + t] = __float2half_rn(dot);
        }
    }
}

// ---------------- dynamic routing: warp-per-n, 3 WU passes (fp16 WU) ----------------
#define ROUT_SMEM ((11520 + 1600 + 160 + 16) * 4)

__device__ __forceinline__ void rout_reduce_squash(
    float* s_red, float* s_v, float* s_scale, const float* acc,
    int tid, int w, int l, float cs) {
    #pragma unroll
    for (int j = 0; j < 5; ++j) s_red[w * 160 + 32 * j + l] = acc[j];
    __syncthreads();
    if (tid < 160) {
        float v = 0.f;
        #pragma unroll
        for (int ww = 0; ww < 10; ++ww) v += s_red[ww * 160 + tid];
        s_v[tid] = v * cs;
    }
    __syncthreads();
    if (tid < NC) {
        float sq = 0.f;
        #pragma unroll
        for (int d = 0; d < DCD; ++d) { float x = s_v[tid * DCD + d]; sq += x * x; }
        s_scale[tid] = sq / (1.f + sq) / sqrtf(sq + 1e-7f);
    }
    __syncthreads();
    if (tid < 160) s_v[tid] *= s_scale[tid >> 4];
    __syncthreads();
}

__global__ void routing_kernel(float* __restrict__ out) {
    extern __shared__ float smf[];
    float* s_b     = smf;
    float* s_red   = smf + 11520;
    float* s_v     = smf + 13120;
    float* s_scale = smf + 13280;
    const int b = blockIdx.x, tid = threadIdx.x;
    const int w = tid >> 5, l = tid & 31;
    const int myh = l >> 4;
    const size_t wub = (size_t)b * NPRIM * 160;
    const unsigned FULL = 0xffffffffu;
    float acc[5];

    #pragma unroll
    for (int j = 0; j < 5; ++j) acc[j] = 0.f;
    for (int n = w; n < NPRIM; n += 10) {
        const __half* row = g_WUh + wub + (size_t)n * 160;
        #pragma unroll
        for (int j = 0; j < 5; ++j) acc[j] += __half2float(row[l + 32 * j]);
    }
    rout_reduce_squash(s_red, s_v, s_scale, acc, tid, w, l, 0.1f);

    #pragma unroll
    for (int j = 0; j < 5; ++j) acc[j] = 0.f;
    for (int n = w; n < NPRIM; n += 10) {
        const __half* row = g_WUh + wub + (size_t)n * 160;
        float wv[5], t[5];
        #pragma unroll
        for (int j = 0; j < 5; ++j) wv[j] = __half2float(row[l + 32 * j]);
        #pragma unroll
        for (int j = 0; j < 5; ++j) t[j] = s_v[l + 32 * j] * wv[j];
        #pragma unroll
        for (int j = 0; j < 5; ++j) {
            t[j] += __shfl_xor_sync(FULL, t[j], 8);
            t[j] += __shfl_xor_sync(FULL, t[j], 4);
            t[j] += __shfl_xor_sync(FULL, t[j], 2);
            t[j] += __shfl_xor_sync(FULL, t[j], 1);
            t[j] *= 0.1f;
        }
        float o[5];
        #pragma unroll
        for (int j = 0; j < 5; ++j) o[j] = __shfl_xor_sync(FULL, t[j], 16);
        float selt = t[0], selo = o[0];
        #pragma unroll
        for (int jj = 1; jj < 5; ++jj) {
            bool p = ((l >> 1) == jj);
            selt = p ? t[jj] : selt;
            selo = p ? o[jj] : selo;
        }
        const float bv = (l & 1) ? selo : selt;
        if (l < NC) s_b[n * NC + l] = bv;
        float m = (l < NC) ? bv : -1e30f;
        m = fmaxf(m, __shfl_xor_sync(FULL, m, 16));
        m = fmaxf(m, __shfl_xor_sync(FULL, m, 8));
        m = fmaxf(m, __shfl_xor_sync(FULL, m, 4));
        m = fmaxf(m, __shfl_xor_sync(FULL, m, 2));
        m = fmaxf(m, __shfl_xor_sync(FULL, m, 1));
        float e = (l < NC) ? __expf(bv - m) : 0.f;
        float S = e;
        S += __shfl_xor_sync(FULL, S, 16);
        S += __shfl_xor_sync(FULL, S, 8);
        S += __shfl_xor_sync(FULL, S, 4);
        S += __shfl_xor_sync(FULL, S, 2);
        S += __shfl_xor_sync(FULL, S, 1);
        const float en = e / S;
        #pragma unroll
        for (int j = 0; j < 5; ++j) {
            float cf = __shfl_sync(FULL, en, 2 * j + myh);
            acc[j] += cf * wv[j];
        }
    }
    rout_reduce_squash(s_red, s_v, s_scale, acc, tid, w, l, 1.f);

    #pragma unroll
    for (int j = 0; j < 5; ++j) acc[j] = 0.f;
    for (int n = w; n < NPRIM; n += 10) {
        const __half* row = g_WUh + wub + (size_t)n * 160;
        float wv[5];
        #pragma unroll
        for (int j = 0; j < 5; ++j) wv[j] = __half2float(row[l + 32 * j]);
        const float bv1 = (l < NC) ? s_b[n * NC + l] : 0.f;
        float m1 = (l < NC) ? bv1 : -1e30f;
        m1 = fmaxf(m1, __shfl_xor_sync(FULL, m1, 16));
        m1 = fmaxf(m1, __shfl_xor_sync(FULL, m1, 8));
        m1 = fmaxf(m1, __shfl_xor_sync(FULL, m1, 4));
        m1 = fmaxf(m1, __shfl_xor_sync(FULL, m1, 2));
        m1 = fmaxf(m1, __shfl_xor_sync(FULL, m1, 1));
        float e1 = (l < NC) ? __expf(bv1 - m1) : 0.f;
        float S1 = e1;
        S1 += __shfl_xor_sync(FULL, S1, 16);
        S1 += __shfl_xor_sync(FULL, S1, 8);
        S1 += __shfl_xor_sync(FULL, S1, 4);
        S1 += __shfl_xor_sync(FULL, S1, 2);
        S1 += __shfl_xor_sync(FULL, S1, 1);
        const float en1 = e1 / S1;
        float t2[5];
        #pragma unroll
        for (int j = 0; j < 5; ++j) {
            float cf1 = __shfl_sync(FULL, en1, 2 * j + myh);
            t2[j] = s_v[l + 32 * j] * cf1 * wv[j];
            t2[j] += __shfl_xor_sync(FULL, t2[j], 8);
            t2[j] += __shfl_xor_sync(FULL, t2[j], 4);
            t2[j] += __shfl_xor_sync(FULL, t2[j], 2);
            t2[j] += __shfl_xor_sync(FULL, t2[j], 1);
        }
        float o2[5];
        #pragma unroll
        for (int j = 0; j < 5; ++j) o2[j] = __shfl_xor_sync(FULL, t2[j], 16);
        float selt = t2[0], selo = o2[0];
        #pragma unroll
        for (int jj = 1; jj < 5; ++jj) {
            bool p = ((l >> 1) == jj);
            selt = p ? t2[jj] : selt;
            selo = p ? o2[jj] : selo;
        }
        const float b2v = bv1 + ((l & 1) ? selo : selt);
        float m2 = (l < NC) ? b2v : -1e30f;
        m2 = fmaxf(m2, __shfl_xor_sync(FULL, m2, 16));
        m2 = fmaxf(m2, __shfl_xor_sync(FULL, m2, 8));
        m2 = fmaxf(m2, __shfl_xor_sync(FULL, m2, 4));
        m2 = fmaxf(m2, __shfl_xor_sync(FULL, m2, 2));
        m2 = fmaxf(m2, __shfl_xor_sync(FULL, m2, 1));
        float e2 = (l < NC) ? __expf(b2v - m2) : 0.f;
        float S2 = e2;
        S2 += __shfl_xor_sync(FULL, S2, 16);
        S2 += __shfl_xor_sync(FULL, S2, 8);
        S2 += __shfl_xor_sync(FULL, S2, 4);
        S2 += __shfl_xor_sync(FULL, S2, 2);
        S2 += __shfl_xor_sync(FULL, S2, 1);
        const float en2 = e2 / S2;
        #pragma unroll
        for (int j = 0; j < 5; ++j) {
            float cf2 = __shfl_sync(FULL, en2, 2 * j + myh);
            acc[j] += cf2 * wv[j];
        }
    }
    rout_reduce_squash(s_red, s_v, s_scale, acc, tid, w, l, 1.f);

    if (tid < 160) g_v[b * 160 + tid] = s_v[tid];
    if (tid < NC) {
        float sq = 0.f;
        #pragma unroll
        for (int d = 0; d < DCD; ++d) { float x = s_v[tid * DCD + d]; sq += x * x; }
        out[b * NC + tid] = sqrtf(sq);
    }
}

// ---------------- masked decoder: 4 images per block, fp16 weights (proven) ----------------
__global__ void decoder_kernel(const int* __restrict__ labels,
                               const float* __restrict__ w1, const float* __restrict__ bb1,
                               const float* __restrict__ bb2,
                               const float* __restrict__ bb3,
                               float* __restrict__ out) {
    __shared__ float h0[4][DCD];
    __shared__ float h1[4][512];
    __shared__ float h2[4][1024];
    __shared__ int   lab[4];
    const int t = threadIdx.x;
    const int b0 = blockIdx.x * 4;
    if (t < 4) lab[t] = labels[b0 + t];
    __syncthreads();
    if (t < 64) {
        int i = t >> 4, d = t & 15;
        h0[i][d] = g_v[(b0 + i) * 160 + lab[i] * DCD + d];
    }
    __syncthreads();
    for (int j = t; j < 512; j += 256) {
        float a[4];
        #pragma unroll
        for (int i = 0; i < 4; ++i) a[i] = bb1[j];
        #pragma unroll
        for (int k = 0; k < DCD; ++k) {
            #pragma unroll
            for (int i = 0; i < 4; ++i)
                a[i] += h0[i][k] * w1[(lab[i] * DCD + k) * 512 + j];
        }
        #pragma unroll
        for (int i = 0; i < 4; ++i) h1[i][j] = fmaxf(a[i], 0.f);
    }
    __syncthreads();
    for (int j = t; j < 1024; j += 256) {
        float a[4];
        #pragma unroll
        for (int i = 0; i < 4; ++i) a[i] = bb2[j];
        for (int k = 0; k < 512; ++k) {
            float wv = __half2float(g_w2h[k * 1024 + j]);
            #pragma unroll
            for (int i = 0; i < 4; ++i) a[i] += h1[i][k] * wv;
        }
        #pragma unroll
        for (int i = 0; i < 4; ++i) h2[i][j] = fmaxf(a[i], 0.f);
    }
    __syncthreads();
    for (int j = t; j < 784; j += 256) {
        float a[4];
        #pragma unroll
        for (int i = 0; i < 4; ++i) a[i] = bb3[j];
        for (int k = 0; k < 1024; ++k) {
            float wv = __half2float(g_w3h[k * 784 + j]);
            #pragma unroll
            for (int i = 0; i < 4; ++i) a[i] += h2[i][k] * wv;
        }
        #pragma unroll
        for (int i = 0; i < 4; ++i)
            out[BATCH * NC + (b0 + i) * 784 + j] = 1.f / (1.f + __expf(-a[i]));
    }
}

// ---------------- launch ----------------
extern "C" void kernel_launch(void* const* d_in, const int* in_sizes, int n_in,
                              void* d_out, int out_size) {
    const float* inputs  = (const float*)d_in[0];
    const int*   labels  = (const int*)d_in[1];
    const float* conv1_w = (const float*)d_in[2];
    const float* conv1_b = (const float*)d_in[3];
    const float* pc_w    = (const float*)d_in[4];
    const float* pc_b    = (const float*)d_in[5];
    const float* rw      = (const float*)d_in[6];
    const float* dw1     = (const float*)d_in[7];
    const float* db1     = (const float*)d_in[8];
    const float* dw2     = (const float*)d_in[9];
    const float* db2     = (const float*)d_in[10];
    const float* dw3     = (const float*)d_in[11];
    const float* db3     = (const float*)d_in[12];
    float* out = (float*)d_out;

    convert_c1w_kernel<<<256, 128>>>(conv1_w);
    convert_w_kernel<<<C1, 256>>>(pc_w);
    convert_dec_kernel<<<(1024 * 784 + 255) / 256, 256>>>(dw2, dw3);

    cudaFuncSetAttribute(conv1_gemm_kernel, cudaFuncAttributeMaxDynamicSharedMemorySize, C1_SMEM);
    conv1_gemm_kernel<<<dim3(800, 2), 512, C1_SMEM>>>(inputs, conv1_b);

    cudaFuncSetAttribute(gemm_kernel, cudaFuncAttributeMaxDynamicSharedMemorySize, GEMM_SMEM);
    gemm_kernel<<<dim3(144, 2), 256, GEMM_SMEM>>>(pc_b);

    squash_u_kernel<<<NPRIM, 256>>>();
    wu_kernel<<<NPRIM, 160>>>(rw);

    cudaFuncSetAttribute(routing_kernel, cudaFuncAttributeMaxDynamicSharedMemorySize, ROUT_SMEM);
    routing_kernel<<<BATCH, 320, ROUT_SMEM>>>(out);

    decoder_kernel<<<BATCH / 4, 256>>>(labels, dw1, db1, db2, db3, out);
}

// round 16
// speedup vs baseline: 1.1456x; 1.1456x over previous
#include <cuda_runtime.h>
#include <cuda_fp16.h>
#include <math.h>
#include <stdint.h>

#define BATCH 256
#define C1 256
#define IMGD 28
#define NPRIM 1152
#define NC 10
#define PCD 8
#define DCD 16
#define KTOT 20736           // 81 r * 256 ic  (k = r*256 + ic)
#define MTOT 9216            // 256 b * 36 sp
#define NKT (KTOT / 64)      // 324

// ---------------- scratch ----------------
__device__ __align__(16) __half g_xh[(size_t)BATCH * 400 * C1];  // conv1 out fp16 [b][px][ic]
__device__ __align__(16) __half g_Bh[(size_t)C1 * KTOT];         // pc_w fp16 [oc][k]
__device__ __align__(16) __half g_c1w[256 * 128];                // conv1_w fp16 [oc][k pad 128]
__device__ float g_pc[(size_t)MTOT * C1];                        // pc conv out [m][oc]
__device__ float g_u[BATCH * NPRIM * PCD];                       // squashed, [n][b][p]
__device__ __align__(16) __half g_WUh[(size_t)BATCH * NPRIM * NC * DCD];  // u_hat fp16
__device__ float g_v[BATCH * NC * DCD];
__device__ __align__(16) __half g_w2h[512 * 1024];
__device__ __align__(16) __half g_w3h[1024 * 784];

__device__ __forceinline__ uint32_t smem_u32(const void* p) {
    uint32_t a;
    asm("{ .reg .u64 t; cvta.to.shared.u64 t, %1; cvt.u32.u64 %0, t; }" : "=r"(a) : "l"(p));
    return a;
}
#define CP_ASYNC16(sa, ga) \
    asm volatile("cp.async.cg.shared.global [%0], [%1], 16;" :: "r"(sa), "l"(ga))
#define CP_COMMIT() asm volatile("cp.async.commit_group;" ::: "memory")
#define CP_WAIT1()  asm volatile("cp.async.wait_group 1;" ::: "memory")
#define CP_WAIT0()  asm volatile("cp.async.wait_group 0;" ::: "memory")
#define LDMX4(r0, r1, r2, r3, a) \
    asm volatile("ldmatrix.sync.aligned.m8n8.x4.shared.b16 {%0,%1,%2,%3}, [%4];" \
        : "=r"(r0), "=r"(r1), "=r"(r2), "=r"(r3) : "r"(a))
#define MMAF16(c, a, b0, b1) \
    asm volatile("mma.sync.aligned.m16n8k16.row.col.f32.f16.f16.f32 " \
        "{%0,%1,%2,%3},{%4,%5,%6,%7},{%8,%9},{%0,%1,%2,%3};" \
        : "+f"((c)[0]), "+f"((c)[1]), "+f"((c)[2]), "+f"((c)[3]) \
        : "r"((a)[0]), "r"((a)[1]), "r"((a)[2]), "r"((a)[3]), "r"(b0), "r"(b1))

// ---------------- conv1_w -> fp16, [oc][128] zero-padded ----------------
__global__ void convert_c1w_kernel(const float* __restrict__ w) {
    const int oc = blockIdx.x, k = threadIdx.x;
    g_c1w[oc * 128 + k] = (k < 81) ? __float2half_rn(w[oc * 81 + k]) : __half(0);
}

// ---------------- pc_w -> fp16 transposed per-oc (coalesced both sides, verified) ----------------
__global__ void convert_w_kernel(const float* __restrict__ w) {
    __shared__ __half sw[KTOT];
    const int oc = blockIdx.x, t = threadIdx.x;   // 256 threads
    const float* src = w + (size_t)oc * KTOT;
    for (int i = t; i < KTOT; i += 256) sw[i] = __float2half_rn(src[i]);
    __syncthreads();
    __half* dst = g_Bh + (size_t)oc * KTOT;
    for (int r = 0; r < 81; ++r) dst[r * 256 + t] = sw[t * 81 + r];
}

// ---------------- decoder w2/w3 -> fp16 ----------------
__global__ void convert_dec_kernel(const float* __restrict__ w2,
                                   const float* __restrict__ w3) {
    const int i = blockIdx.x * 256 + threadIdx.x;
    if (i < 512 * 1024) g_w2h[i] = __float2half_rn(w2[i]);
    if (i < 1024 * 784) g_w3h[i] = __float2half_rn(w3[i]);
}

// ---------------- conv1 as implicit GEMM: M=102400, N=256, K=81->128 ----------------
#define C1_SMEM (8192 + 65536)

__global__ void __launch_bounds__(512, 2) conv1_gemm_kernel(const float* __restrict__ in,
                                                            const float* __restrict__ bias) {
    extern __shared__ char sm[];
    float* s_bias = (float*)sm;
    float* s_img = (float*)(sm + 1024);
    const uint32_t smb = smem_u32(sm);
    const int tid = threadIdx.x, lane = tid & 31, wid = tid >> 5;
    const int mtile = blockIdx.x, ntile = blockIdx.y;
    if (tid < 128) s_bias[tid] = bias[ntile * 128 + tid];

    const int m0 = mtile * 128;
    const int b0 = m0 / 400;
    const int b1 = (b0 + 1 < BATCH) ? b0 + 1 : b0;

    #pragma unroll
    for (int i = 0; i < 4; ++i) {
        const int lin = tid + i * 512;
        const int row = lin >> 4, c16 = lin & 15;
        const int kc = c16 >> 3, ch = c16 & 7;
        const uint32_t dst = smb + 8192 + kc * 32768 + 16384
                           + row * 128 + ((ch ^ (row & 7)) << 4);
        const size_t src = (size_t)(ntile * 128 + row) * 256 + kc * 128 + ch * 16;
        CP_ASYNC16(dst, (const char*)g_c1w + src);
    }
    CP_COMMIT();

    for (int i = tid; i < 2 * 784; i += 512) {
        const int im = (i >= 784);
        s_img[i] = in[(im ? b1 : b0) * 784 + (i - im * 784)];
    }
    __syncthreads();

    {
        const int row = tid >> 2;
        const int cb = (tid & 3) * 32;
        const int m = m0 + row;
        const int bb = m / 400, px = m - bb * 400;
        const int ibase = ((bb == b0) ? 0 : 784) + (px / 20) * 28 + (px % 20);
        #pragma unroll
        for (int p = 0; p < 16; ++p) {
            const int k0 = cb + 2 * p;
            float v0 = 0.f, v1 = 0.f;
            if (k0 < 81) {
                int ky = (k0 * 57) >> 9, kx = k0 - ky * 9;
                v0 = s_img[ibase + ky * 28 + kx];
            }
            if (k0 + 1 < 81) {
                int ky = ((k0 + 1) * 57) >> 9, kx = k0 + 1 - ky * 9;
                v1 = s_img[ibase + ky * 28 + kx];
            }
            const int within = k0 & 63;
            const int off = 8192 + (k0 >> 6) * 32768 + row * 128
                          + (((within >> 3) ^ (row & 7)) << 4) + (within & 7) * 2;
            *(__half2*)(sm + off) = __floats2half2_rn(v0, v1);
        }
    }
    CP_WAIT0();
    __syncthreads();

    const int warp_m = wid >> 2, warp_n = wid & 3;
    int a_off[2], a_sw[2];
    #pragma unroll
    for (int sub = 0; sub < 2; ++sub) {
        int row = warp_m * 32 + sub * 16 + (lane & 15);
        a_off[sub] = row * 128; a_sw[sub] = row & 7;
    }
    const int a_cb = lane >> 4;
    int b_off[2], b_sw[2];
    #pragma unroll
    for (int j = 0; j < 2; ++j) {
        int row = warp_n * 32 + j * 16 + ((lane >> 4) << 3) + (lane & 7);
        b_off[j] = row * 128; b_sw[j] = row & 7;
    }
    const int b_cb = (lane >> 3) & 1;

    float acc[2][4][4];
    #pragma unroll
    for (int m = 0; m < 2; ++m)
        #pragma unroll
        for (int j = 0; j < 4; ++j)
            #pragma unroll
            for (int q = 0; q < 4; ++q) acc[m][j][q] = 0.f;

    #pragma unroll
    for (int t = 0; t < 2; ++t) {
        const uint32_t sA = smb + 8192 + t * 32768;
        const uint32_t sB = sA + 16384;
        #pragma unroll
        for (int ks = 0; ks < 4; ++ks) {
            uint32_t a[2][4], bfr[2][4];
            #pragma unroll
            for (int sub = 0; sub < 2; ++sub) {
                uint32_t co = ((((ks << 1) + a_cb) ^ a_sw[sub]) << 4);
                LDMX4(a[sub][0], a[sub][1], a[sub][2], a[sub][3], sA + a_off[sub] + co);
            }
            #pragma unroll
            for (int j = 0; j < 2; ++j) {
                uint32_t co = ((((ks << 1) + b_cb) ^ b_sw[j]) << 4);
                LDMX4(bfr[j][0], bfr[j][1], bfr[j][2], bfr[j][3], sB + b_off[j] + co);
            }
            #pragma unroll
            for (int msub = 0; msub < 2; ++msub)
                #pragma unroll
                for (int j = 0; j < 2; ++j) {
                    MMAF16(acc[msub][2 * j],     a[msub], bfr[j][0], bfr[j][1]);
                    MMAF16(acc[msub][2 * j + 1], a[msub], bfr[j][2], bfr[j][3]);
                }
        }
    }

    const int r = lane >> 2, cpair = (lane & 3) * 2;
    #pragma unroll
    for (int msub = 0; msub < 2; ++msub) {
        const int gm0 = m0 + warp_m * 32 + msub * 16 + r;
        #pragma unroll
        for (int j = 0; j < 4; ++j) {
            const int ln = warp_n * 32 + j * 8 + cpair;
            const int gn = ntile * 128 + ln;
            const float bb0 = s_bias[ln], bb1 = s_bias[ln + 1];
            __half2 v0 = __floats2half2_rn(fmaxf(acc[msub][j][0] + bb0, 0.f),
                                           fmaxf(acc[msub][j][1] + bb1, 0.f));
            __half2 v1 = __floats2half2_rn(fmaxf(acc[msub][j][2] + bb0, 0.f),
                                           fmaxf(acc[msub][j][3] + bb1, 0.f));
            *(__half2*)&g_xh[(size_t)gm0 * C1 + gn] = v0;
            *(__half2*)&g_xh[(size_t)(gm0 + 8) * C1 + gn] = v1;
        }
    }
}

// ---------------- implicit fp16 GEMM: 64x128 tile, 256 thr, 2 CTA/SM, 2-stage (r6 schedule) ----------------
#define STG 24576
#define GEMM_SMEM (1024 + 2 * STG)

__global__ void __launch_bounds__(256, 2) gemm_kernel(const float* __restrict__ bias) {
    extern __shared__ char sm[];
    float* s_bias = (float*)sm;
    const uint32_t smb = smem_u32(sm);
    const int tid = threadIdx.x, lane = tid & 31, wid = tid >> 5;
    const int mtile = blockIdx.x, ntile = blockIdx.y;
    if (tid < 128) s_bias[tid] = bias[ntile * 128 + tid];

    const char* Bh = (const char*)g_Bh + (size_t)ntile * 128 * (KTOT * 2);

    int abase[2], aso2[2];
    #pragma unroll
    for (int i = 0; i < 2; ++i) {
        const int lin = tid + i * 256;
        const int ar = lin >> 3, ch = lin & 7;
        const int m = mtile * 64 + ar;
        const int bb = m / 36, sp = m - bb * 36;
        const int pbase = (2 * (sp / 6)) * 20 + 2 * (sp % 6);
        abase[i] = ((bb * 400 + pbase) << 8) + ch * 8;
        aso2[i] = ar * 128 + ((ch ^ (ar & 7)) << 4);
    }
    int brow[4], bso[4], bch[4];
    #pragma unroll
    for (int i = 0; i < 4; ++i) {
        int lin = tid + i * 256;
        brow[i] = lin >> 3; bch[i] = lin & 7;
        bso[i] = brow[i] * 128 + ((bch[i] ^ (brow[i] & 7)) << 4);
    }

    const int warp_m = wid >> 2, warp_n = wid & 3;
    int a_off[2], a_sw[2];
    #pragma unroll
    for (int sub = 0; sub < 2; ++sub) {
        int row = warp_m * 32 + sub * 16 + (lane & 15);
        a_off[sub] = row * 128; a_sw[sub] = row & 7;
    }
    const int a_cb = lane >> 4;
    int b_off[2], b_sw[2];
    #pragma unroll
    for (int j = 0; j < 2; ++j) {
        int row = warp_n * 32 + j * 16 + ((lane >> 4) << 3) + (lane & 7);
        b_off[j] = row * 128; b_sw[j] = row & 7;
    }
    const int b_cb = (lane >> 3) & 1;

    float acc[2][4][4];
    #pragma unroll
    for (int m = 0; m < 2; ++m)
        #pragma unroll
        for (int j = 0; j < 4; ++j)
            #pragma unroll
            for (int q = 0; q < 4; ++q) acc[m][j][q] = 0.f;

    auto issue = [&](int kk, int buf) {
        const uint32_t sA = smb + 1024 + buf * STG;
        const uint32_t sB = sA + 8192;
        const int r = kk >> 2, icq = kk & 3;
        const int dy = (r * 57) >> 9;
        const int poff = ((dy * 20 + (r - dy * 9)) << 8) + (icq << 6);
        #pragma unroll
        for (int i = 0; i < 2; ++i) {
            const size_t e = (size_t)(abase[i] + poff) * 2;
            CP_ASYNC16(sA + aso2[i], (const char*)g_xh + e);
        }
        const size_t kbyte = (size_t)kk * 128;
        #pragma unroll
        for (int i = 0; i < 4; ++i) {
            const size_t go = (size_t)brow[i] * (KTOT * 2) + kbyte + bch[i] * 16;
            CP_ASYNC16(sB + bso[i], Bh + go);
        }
        CP_COMMIT();
    };

    issue(0, 0);
    for (int t = 0; t < NKT; ++t) {
        if (t + 1 < NKT) issue(t + 1, (t + 1) & 1);
        else CP_COMMIT();
        CP_WAIT1();
        __syncthreads();
        const uint32_t sA = smb + 1024 + (t & 1) * STG;
        const uint32_t sB = sA + 8192;
        #pragma unroll
        for (int ks = 0; ks < 4; ++ks) {
            uint32_t a[2][4], bfr[2][4];
            #pragma unroll
            for (int sub = 0; sub < 2; ++sub) {
                uint32_t co = ((((ks << 1) + a_cb) ^ a_sw[sub]) << 4);
                LDMX4(a[sub][0], a[sub][1], a[sub][2], a[sub][3], sA + a_off[sub] + co);
            }
            #pragma unroll
            for (int j = 0; j < 2; ++j) {
                uint32_t co = ((((ks << 1) + b_cb) ^ b_sw[j]) << 4);
                LDMX4(bfr[j][0], bfr[j][1], bfr[j][2], bfr[j][3], sB + b_off[j] + co);
            }
            #pragma unroll
            for (int msub = 0; msub < 2; ++msub)
                #pragma unroll
                for (int j = 0; j < 2; ++j) {
                    MMAF16(acc[msub][2 * j],     a[msub], bfr[j][0], bfr[j][1]);
                    MMAF16(acc[msub][2 * j + 1], a[msub], bfr[j][2], bfr[j][3]);
                }
        }
        __syncthreads();
    }
    CP_WAIT0();

    const int r = lane >> 2, cpair = (lane & 3) * 2;
    #pragma unroll
    for (int msub = 0; msub < 2; ++msub) {
        const int gm0 = mtile * 64 + warp_m * 32 + msub * 16 + r;
        #pragma unroll
        for (int j = 0; j < 4; ++j) {
            const int ln = warp_n * 32 + j * 8 + cpair;
            const int gn = ntile * 128 + ln;
            const float b0 = s_bias[ln], b1 = s_bias[ln + 1];
            float2 v0 = {acc[msub][j][0] + b0, acc[msub][j][1] + b1};
            float2 v1 = {acc[msub][j][2] + b0, acc[msub][j][3] + b1};
            *(float2*)&g_pc[(size_t)gm0 * C1 + gn] = v0;
            *(float2*)&g_pc[(size_t)(gm0 + 8) * C1 + gn] = v1;
        }
    }
}

// ---------------- squash ----------------
__global__ void squash_u_kernel() {
    __shared__ float s[8][256];
    const int tid = threadIdx.x, w = tid >> 5, l = tid & 31;
    const int m = blockIdx.x * 8 + w;
    const float* row = g_pc + (size_t)m * C1;
    float4 r0 = ((const float4*)row)[l * 2];
    float4 r1 = ((const float4*)row)[l * 2 + 1];
    *(float4*)&s[w][l * 8]     = r0;
    *(float4*)&s[w][l * 8 + 4] = r1;
    __syncwarp();
    float v[PCD];
    float sq = 0.f;
    #pragma unroll
    for (int d = 0; d < PCD; ++d) {
        v[d] = s[w][d * 32 + l];
        sq += v[d] * v[d];
    }
    const float sc = sq / (1.f + sq) / sqrtf(sq + 1e-7f);
    const int b = m / 36, sp = m % 36;
    const int n = l * 36 + sp;
    float4 o0 = {v[0] * sc, v[1] * sc, v[2] * sc, v[3] * sc};
    float4 o1 = {v[4] * sc, v[5] * sc, v[6] * sc, v[7] * sc};
    float* dst = g_u + ((size_t)n * BATCH + b) * PCD;
    *(float4*)dst = o0;
    *(float4*)(dst + 4) = o1;
}

// ---------------- u_hat -> fp16 ----------------
__global__ void wu_kernel(const float* __restrict__ W) {
    __shared__ float s_u[64 * PCD];
    const int n = blockIdx.x;
    const int t = threadIdx.x;
    float wr[PCD];
    #pragma unroll
    for (int p = 0; p < PCD; ++p) wr[p] = W[n * (NC * DCD * PCD) + t * PCD + p];
    for (int b0 = 0; b0 < BATCH; b0 += 64) {
        __syncthreads();
        const uint4* src = (const uint4*)(g_u + ((size_t)n * BATCH + b0) * PCD);
        for (int i = t; i < 128; i += 160) ((uint4*)s_u)[i] = src[i];
        __syncthreads();
        for (int bb = 0; bb < 64; ++bb) {
            const float* up = &s_u[bb * PCD];
            float dot = 0.f;
            #pragma unroll
            for (int p = 0; p < PCD; ++p) dot += wr[p] * up[p];
            g_WUh[((size_t)((b0 + bb) * NPRIM + n)) * 160 + t] = __float2half_rn(dot);
        }
    }
}

// ---------------- dynamic routing: warp-per-n, 3 WU passes (fp16 WU) ----------------
#define ROUT_SMEM ((11520 + 1600 + 160 + 16) * 4)

__device__ __forceinline__ void rout_reduce_squash(
    float* s_red, float* s_v, float* s_scale, const float* acc,
    int tid, int w, int l, float cs) {
    #pragma unroll
    for (int j = 0; j < 5; ++j) s_red[w * 160 + 32 * j + l] = acc[j];
    __syncthreads();
    if (tid < 160) {
        float v = 0.f;
        #pragma unroll
        for (int ww = 0; ww < 10; ++ww) v += s_red[ww * 160 + tid];
        s_v[tid] = v * cs;
    }
    __syncthreads();
    if (tid < NC) {
        float sq = 0.f;
        #pragma unroll
        for (int d = 0; d < DCD; ++d) { float x = s_v[tid * DCD + d]; sq += x * x; }
        s_scale[tid] = sq / (1.f + sq) / sqrtf(sq + 1e-7f);
    }
    __syncthreads();
    if (tid < 160) s_v[tid] *= s_scale[tid >> 4];
    __syncthreads();
}

__global__ void routing_kernel(float* __restrict__ out) {
    extern __shared__ float smf[];
    float* s_b     = smf;
    float* s_red   = smf + 11520;
    float* s_v     = smf + 13120;
    float* s_scale = smf + 13280;
    const int b = blockIdx.x, tid = threadIdx.x;
    const int w = tid >> 5, l = tid & 31;
    const int myh = l >> 4;
    const size_t wub = (size_t)b * NPRIM * 160;
    const unsigned FULL = 0xffffffffu;
    float acc[5];

    #pragma unroll
    for (int j = 0; j < 5; ++j) acc[j] = 0.f;
    for (int n = w; n < NPRIM; n += 10) {
        const __half* row = g_WUh + wub + (size_t)n * 160;
        #pragma unroll
        for (int j = 0; j < 5; ++j) acc[j] += __half2float(row[l + 32 * j]);
    }
    rout_reduce_squash(s_red, s_v, s_scale, acc, tid, w, l, 0.1f);

    #pragma unroll
    for (int j = 0; j < 5; ++j) acc[j] = 0.f;
    for (int n = w; n < NPRIM; n += 10) {
        const __half* row = g_WUh + wub + (size_t)n * 160;
        float wv[5], t[5];
        #pragma unroll
        for (int j = 0; j < 5; ++j) wv[j] = __half2float(row[l + 32 * j]);
        #pragma unroll
        for (int j = 0; j < 5; ++j) t[j] = s_v[l + 32 * j] * wv[j];
        #pragma unroll
        for (int j = 0; j < 5; ++j) {
            t[j] += __shfl_xor_sync(FULL, t[j], 8);
            t[j] += __shfl_xor_sync(FULL, t[j], 4);
            t[j] += __shfl_xor_sync(FULL, t[j], 2);
            t[j] += __shfl_xor_sync(FULL, t[j], 1);
            t[j] *= 0.1f;
        }
        float o[5];
        #pragma unroll
        for (int j = 0; j < 5; ++j) o[j] = __shfl_xor_sync(FULL, t[j], 16);
        float selt = t[0], selo = o[0];
        #pragma unroll
        for (int jj = 1; jj < 5; ++jj) {
            bool p = ((l >> 1) == jj);
            selt = p ? t[jj] : selt;
            selo = p ? o[jj] : selo;
        }
        const float bv = (l & 1) ? selo : selt;
        if (l < NC) s_b[n * NC + l] = bv;
        float m = (l < NC) ? bv : -1e30f;
        m = fmaxf(m, __shfl_xor_sync(FULL, m, 16));
        m = fmaxf(m, __shfl_xor_sync(FULL, m, 8));
        m = fmaxf(m, __shfl_xor_sync(FULL, m, 4));
        m = fmaxf(m, __shfl_xor_sync(FULL, m, 2));
        m = fmaxf(m, __shfl_xor_sync(FULL, m, 1));
        float e = (l < NC) ? __expf(bv - m) : 0.f;
        float S = e;
        S += __shfl_xor_sync(FULL, S, 16);
        S += __shfl_xor_sync(FULL, S, 8);
        S += __shfl_xor_sync(FULL, S, 4);
        S += __shfl_xor_sync(FULL, S, 2);
        S += __shfl_xor_sync(FULL, S, 1);
        const float en = e / S;
        #pragma unroll
        for (int j = 0; j < 5; ++j) {
            float cf = __shfl_sync(FULL, en, 2 * j + myh);
            acc[j] += cf * wv[j];
        }
    }
    rout_reduce_squash(s_red, s_v, s_scale, acc, tid, w, l, 1.f);

    #pragma unroll
    for (int j = 0; j < 5; ++j) acc[j] = 0.f;
    for (int n = w; n < NPRIM; n += 10) {
        const __half* row = g_WUh + wub + (size_t)n * 160;
        float wv[5];
        #pragma unroll
        for (int j = 0; j < 5; ++j) wv[j] = __half2float(row[l + 32 * j]);
        const float bv1 = (l < NC) ? s_b[n * NC + l] : 0.f;
        float m1 = (l < NC) ? bv1 : -1e30f;
        m1 = fmaxf(m1, __shfl_xor_sync(FULL, m1, 16));
        m1 = fmaxf(m1, __shfl_xor_sync(FULL, m1, 8));
        m1 = fmaxf(m1, __shfl_xor_sync(FULL, m1, 4));
        m1 = fmaxf(m1, __shfl_xor_sync(FULL, m1, 2));
        m1 = fmaxf(m1, __shfl_xor_sync(FULL, m1, 1));
        float e1 = (l < NC) ? __expf(bv1 - m1) : 0.f;
        float S1 = e1;
        S1 += __shfl_xor_sync(FULL, S1, 16);
        S1 += __shfl_xor_sync(FULL, S1, 8);
        S1 += __shfl_xor_sync(FULL, S1, 4);
        S1 += __shfl_xor_sync(FULL, S1, 2);
        S1 += __shfl_xor_sync(FULL, S1, 1);
        const float en1 = e1 / S1;
        float t2[5];
        #pragma unroll
        for (int j = 0; j < 5; ++j) {
            float cf1 = __shfl_sync(FULL, en1, 2 * j + myh);
            t2[j] = s_v[l + 32 * j] * cf1 * wv[j];
            t2[j] += __shfl_xor_sync(FULL, t2[j], 8);
            t2[j] += __shfl_xor_sync(FULL, t2[j], 4);
            t2[j] += __shfl_xor_sync(FULL, t2[j], 2);
            t2[j] += __shfl_xor_sync(FULL, t2[j], 1);
        }
        float o2[5];
        #pragma unroll
        for (int j = 0; j < 5; ++j) o2[j] = __shfl_xor_sync(FULL, t2[j], 16);
        float selt = t2[0], selo = o2[0];
        #pragma unroll
        for (int jj = 1; jj < 5; ++jj) {
            bool p = ((l >> 1) == jj);
            selt = p ? t2[jj] : selt;
            selo = p ? o2[jj] : selo;
        }
        const float b2v = bv1 + ((l & 1) ? selo : selt);
        float m2 = (l < NC) ? b2v : -1e30f;
        m2 = fmaxf(m2, __shfl_xor_sync(FULL, m2, 16));
        m2 = fmaxf(m2, __shfl_xor_sync(FULL, m2, 8));
        m2 = fmaxf(m2, __shfl_xor_sync(FULL, m2, 4));
        m2 = fmaxf(m2, __shfl_xor_sync(FULL, m2, 2));
        m2 = fmaxf(m2, __shfl_xor_sync(FULL, m2, 1));
        float e2 = (l < NC) ? __expf(b2v - m2) : 0.f;
        float S2 = e2;
        S2 += __shfl_xor_sync(FULL, S2, 16);
        S2 += __shfl_xor_sync(FULL, S2, 8);
        S2 += __shfl_xor_sync(FULL, S2, 4);
        S2 += __shfl_xor_sync(FULL, S2, 2);
        S2 += __shfl_xor_sync(FULL, S2, 1);
        const float en2 = e2 / S2;
        #pragma unroll
        for (int j = 0; j < 5; ++j) {
            float cf2 = __shfl_sync(FULL, en2, 2 * j + myh);
            acc[j] += cf2 * wv[j];
        }
    }
    rout_reduce_squash(s_red, s_v, s_scale, acc, tid, w, l, 1.f);

    if (tid < 160) g_v[b * 160 + tid] = s_v[tid];
    if (tid < NC) {
        float sq = 0.f;
        #pragma unroll
        for (int d = 0; d < DCD; ++d) { float x = s_v[tid * DCD + d]; sq += x * x; }
        out[b * NC + tid] = sqrtf(sq);
    }
}

// ---------------- masked decoder: 2 images per block, fp16 weights (r12 proven) ----------------
__global__ void decoder_kernel(const int* __restrict__ labels,
                               const float* __restrict__ w1, const float* __restrict__ bb1,
                               const float* __restrict__ bb2,
                               const float* __restrict__ bb3,
                               float* __restrict__ out) {
    __shared__ float h0[2][DCD];
    __shared__ float h1[2][512];
    __shared__ float h2[2][1024];
    __shared__ int   lab[2];
    const int t = threadIdx.x;
    const int b0 = blockIdx.x * 2;
    if (t < 2) lab[t] = labels[b0 + t];
    __syncthreads();
    if (t < 32) {
        int i = t >> 4, d = t & 15;
        h0[i][d] = g_v[(b0 + i) * 160 + lab[i] * DCD + d];
    }
    __syncthreads();
    for (int j = t; j < 512; j += 256) {
        float a[2];
        #pragma unroll
        for (int i = 0; i < 2; ++i) a[i] = bb1[j];
        #pragma unroll
        for (int k = 0; k < DCD; ++k) {
            #pragma unroll
            for (int i = 0; i < 2; ++i)
                a[i] += h0[i][k] * w1[(lab[i] * DCD + k) * 512 + j];
        }
        #pragma unroll
        for (int i = 0; i < 2; ++i) h1[i][j] = fmaxf(a[i], 0.f);
    }
    __syncthreads();
    for (int j = t; j < 1024; j += 256) {
        float a[2];
        #pragma unroll
        for (int i = 0; i < 2; ++i) a[i] = bb2[j];
        for (int k = 0; k < 512; ++k) {
            float wv = __half2float(g_w2h[k * 1024 + j]);
            #pragma unroll
            for (int i = 0; i < 2; ++i) a[i] += h1[i][k] * wv;
        }
        #pragma unroll
        for (int i = 0; i < 2; ++i) h2[i][j] = fmaxf(a[i], 0.f);
    }
    __syncthreads();
    for (int j = t; j < 784; j += 256) {
        float a[2];
        #pragma unroll
        for (int i = 0; i < 2; ++i) a[i] = bb3[j];
        for (int k = 0; k < 1024; ++k) {
            float wv = __half2float(g_w3h[k * 784 + j]);
            #pragma unroll
            for (int i = 0; i < 2; ++i) a[i] += h2[i][k] * wv;
        }
        #pragma unroll
        for (int i = 0; i < 2; ++i)
            out[BATCH * NC + (b0 + i) * 784 + j] = 1.f / (1.f + __expf(-a[i]));
    }
}

// ---------------- launch ----------------
extern "C" void kernel_launch(void* const* d_in, const int* in_sizes, int n_in,
                              void* d_out, int out_size) {
    const float* inputs  = (const float*)d_in[0];
    const int*   labels  = (const int*)d_in[1];
    const float* conv1_w = (const float*)d_in[2];
    const float* conv1_b = (const float*)d_in[3];
    const float* pc_w    = (const float*)d_in[4];
    const float* pc_b    = (const float*)d_in[5];
    const float* rw      = (const float*)d_in[6];
    const float* dw1     = (const float*)d_in[7];
    const float* db1     = (const float*)d_in[8];
    const float* dw2     = (const float*)d_in[9];
    const float* db2     = (const float*)d_in[10];
    const float* dw3     = (const float*)d_in[11];
    const float* db3     = (const float*)d_in[12];
    float* out = (float*)d_out;

    convert_c1w_kernel<<<256, 128>>>(conv1_w);
    convert_w_kernel<<<C1, 256>>>(pc_w);
    convert_dec_kernel<<<(1024 * 784 + 255) / 256, 256>>>(dw2, dw3);

    cudaFuncSetAttribute(conv1_gemm_kernel, cudaFuncAttributeMaxDynamicSharedMemorySize, C1_SMEM);
    conv1_gemm_kernel<<<dim3(800, 2), 512, C1_SMEM>>>(inputs, conv1_b);

    cudaFuncSetAttribute(gemm_kernel, cudaFuncAttributeMaxDynamicSharedMemorySize, GEMM_SMEM);
    gemm_kernel<<<dim3(144, 2), 256, GEMM_SMEM>>>(pc_b);

    squash_u_kernel<<<NPRIM, 256>>>();
    wu_kernel<<<NPRIM, 160>>>(rw);

    cudaFuncSetAttribute(routing_kernel, cudaFuncAttributeMaxDynamicSharedMemorySize, ROUT_SMEM);
    routing_kernel<<<BATCH, 320, ROUT_SMEM>>>(out);

    decoder_kernel<<<BATCH / 2, 256>>>(labels, dw1, db1, db2, db3, out);
}

// round 17
// speedup vs baseline: 1.3053x; 1.1394x over previous
#include <cuda_runtime.h>
#include <cuda_fp16.h>
#include <math.h>
#include <stdint.h>

#define BATCH 256
#define C1 256
#define IMGD 28
#define NPRIM 1152
#define NC 10
#define PCD 8
#define DCD 16
#define KTOT 20736           // 81 r * 256 ic  (k = r*256 + ic)
#define MTOT 9216            // 256 b * 36 sp
#define NKT (KTOT / 64)      // 324

// ---------------- scratch ----------------
__device__ __align__(16) __half g_xh[(size_t)BATCH * 400 * C1];  // conv1 out fp16 [b][px][ic]
__device__ __align__(16) __half g_Bh[(size_t)C1 * KTOT];         // pc_w fp16 [oc][k]
__device__ __align__(16) __half g_c1w[256 * 128];                // conv1_w fp16 [oc][k pad 128]
__device__ float g_pc[(size_t)MTOT * C1];                        // pc conv out [m][oc]
__device__ float g_u[BATCH * NPRIM * PCD];                       // squashed, [n][b][p]
__device__ __align__(16) __half g_WUh[(size_t)BATCH * NPRIM * NC * DCD];  // u_hat fp16
__device__ float g_v[BATCH * NC * DCD];
__device__ __align__(16) __half g_w2h[512 * 1024];
__device__ __align__(16) __half g_w3h[1024 * 784];

__device__ __forceinline__ uint32_t smem_u32(const void* p) {
    uint32_t a;
    asm("{ .reg .u64 t; cvta.to.shared.u64 t, %1; cvt.u32.u64 %0, t; }" : "=r"(a) : "l"(p));
    return a;
}
#define CP_ASYNC16(sa, ga) \
    asm volatile("cp.async.cg.shared.global [%0], [%1], 16;" :: "r"(sa), "l"(ga))
#define CP_COMMIT() asm volatile("cp.async.commit_group;" ::: "memory")
#define CP_WAIT1()  asm volatile("cp.async.wait_group 1;" ::: "memory")
#define CP_WAIT0()  asm volatile("cp.async.wait_group 0;" ::: "memory")
#define LDMX4(r0, r1, r2, r3, a) \
    asm volatile("ldmatrix.sync.aligned.m8n8.x4.shared.b16 {%0,%1,%2,%3}, [%4];" \
        : "=r"(r0), "=r"(r1), "=r"(r2), "=r"(r3) : "r"(a))
#define MMAF16(c, a, b0, b1) \
    asm volatile("mma.sync.aligned.m16n8k16.row.col.f32.f16.f16.f32 " \
        "{%0,%1,%2,%3},{%4,%5,%6,%7},{%8,%9},{%0,%1,%2,%3};" \
        : "+f"((c)[0]), "+f"((c)[1]), "+f"((c)[2]), "+f"((c)[3]) \
        : "r"((a)[0]), "r"((a)[1]), "r"((a)[2]), "r"((a)[3]), "r"(b0), "r"(b1))

// ---------------- conv1_w -> fp16, [oc][128] zero-padded ----------------
__global__ void convert_c1w_kernel(const float* __restrict__ w) {
    const int oc = blockIdx.x, k = threadIdx.x;
    g_c1w[oc * 128 + k] = (k < 81) ? __float2half_rn(w[oc * 81 + k]) : __half(0);
}

// ---------------- pc_w -> fp16 transposed per-oc (coalesced both sides) ----------------
__global__ void convert_w_kernel(const float* __restrict__ w) {
    __shared__ __half sw[KTOT];
    const int oc = blockIdx.x, t = threadIdx.x;   // 256 threads
    const float* src = w + (size_t)oc * KTOT;
    for (int i = t; i < KTOT; i += 256) sw[i] = __float2half_rn(src[i]);
    __syncthreads();
    __half* dst = g_Bh + (size_t)oc * KTOT;
    for (int r = 0; r < 81; ++r) dst[r * 256 + t] = sw[t * 81 + r];
}

// ---------------- decoder w2/w3 -> fp16 ----------------
__global__ void convert_dec_kernel(const float* __restrict__ w2,
                                   const float* __restrict__ w3) {
    const int i = blockIdx.x * 256 + threadIdx.x;
    if (i < 512 * 1024) g_w2h[i] = __float2half_rn(w2[i]);
    if (i < 1024 * 784) g_w3h[i] = __float2half_rn(w3[i]);
}

// ---------------- conv1 as implicit GEMM: M=102400, N=256, K=81->128 ----------------
#define C1_SMEM (8192 + 65536)

__global__ void __launch_bounds__(512, 2) conv1_gemm_kernel(const float* __restrict__ in,
                                                            const float* __restrict__ bias) {
    extern __shared__ char sm[];
    float* s_bias = (float*)sm;
    float* s_img = (float*)(sm + 1024);
    const uint32_t smb = smem_u32(sm);
    const int tid = threadIdx.x, lane = tid & 31, wid = tid >> 5;
    const int mtile = blockIdx.x, ntile = blockIdx.y;
    if (tid < 128) s_bias[tid] = bias[ntile * 128 + tid];

    const int m0 = mtile * 128;
    const int b0 = m0 / 400;
    const int b1 = (b0 + 1 < BATCH) ? b0 + 1 : b0;

    #pragma unroll
    for (int i = 0; i < 4; ++i) {
        const int lin = tid + i * 512;
        const int row = lin >> 4, c16 = lin & 15;
        const int kc = c16 >> 3, ch = c16 & 7;
        const uint32_t dst = smb + 8192 + kc * 32768 + 16384
                           + row * 128 + ((ch ^ (row & 7)) << 4);
        const size_t src = (size_t)(ntile * 128 + row) * 256 + kc * 128 + ch * 16;
        CP_ASYNC16(dst, (const char*)g_c1w + src);
    }
    CP_COMMIT();

    for (int i = tid; i < 2 * 784; i += 512) {
        const int im = (i >= 784);
        s_img[i] = in[(im ? b1 : b0) * 784 + (i - im * 784)];
    }
    __syncthreads();

    {
        const int row = tid >> 2;
        const int cb = (tid & 3) * 32;
        const int m = m0 + row;
        const int bb = m / 400, px = m - bb * 400;
        const int ibase = ((bb == b0) ? 0 : 784) + (px / 20) * 28 + (px % 20);
        #pragma unroll
        for (int p = 0; p < 16; ++p) {
            const int k0 = cb + 2 * p;
            float v0 = 0.f, v1 = 0.f;
            if (k0 < 81) {
                int ky = (k0 * 57) >> 9, kx = k0 - ky * 9;
                v0 = s_img[ibase + ky * 28 + kx];
            }
            if (k0 + 1 < 81) {
                int ky = ((k0 + 1) * 57) >> 9, kx = k0 + 1 - ky * 9;
                v1 = s_img[ibase + ky * 28 + kx];
            }
            const int within = k0 & 63;
            const int off = 8192 + (k0 >> 6) * 32768 + row * 128
                          + (((within >> 3) ^ (row & 7)) << 4) + (within & 7) * 2;
            *(__half2*)(sm + off) = __floats2half2_rn(v0, v1);
        }
    }
    CP_WAIT0();
    __syncthreads();

    const int warp_m = wid >> 2, warp_n = wid & 3;
    int a_off[2], a_sw[2];
    #pragma unroll
    for (int sub = 0; sub < 2; ++sub) {
        int row = warp_m * 32 + sub * 16 + (lane & 15);
        a_off[sub] = row * 128; a_sw[sub] = row & 7;
    }
    const int a_cb = lane >> 4;
    int b_off[2], b_sw[2];
    #pragma unroll
    for (int j = 0; j < 2; ++j) {
        int row = warp_n * 32 + j * 16 + ((lane >> 4) << 3) + (lane & 7);
        b_off[j] = row * 128; b_sw[j] = row & 7;
    }
    const int b_cb = (lane >> 3) & 1;

    float acc[2][4][4];
    #pragma unroll
    for (int m = 0; m < 2; ++m)
        #pragma unroll
        for (int j = 0; j < 4; ++j)
            #pragma unroll
            for (int q = 0; q < 4; ++q) acc[m][j][q] = 0.f;

    #pragma unroll
    for (int t = 0; t < 2; ++t) {
        const uint32_t sA = smb + 8192 + t * 32768;
        const uint32_t sB = sA + 16384;
        #pragma unroll
        for (int ks = 0; ks < 4; ++ks) {
            uint32_t a[2][4], bfr[2][4];
            #pragma unroll
            for (int sub = 0; sub < 2; ++sub) {
                uint32_t co = ((((ks << 1) + a_cb) ^ a_sw[sub]) << 4);
                LDMX4(a[sub][0], a[sub][1], a[sub][2], a[sub][3], sA + a_off[sub] + co);
            }
            #pragma unroll
            for (int j = 0; j < 2; ++j) {
                uint32_t co = ((((ks << 1) + b_cb) ^ b_sw[j]) << 4);
                LDMX4(bfr[j][0], bfr[j][1], bfr[j][2], bfr[j][3], sB + b_off[j] + co);
            }
            #pragma unroll
            for (int msub = 0; msub < 2; ++msub)
                #pragma unroll
                for (int j = 0; j < 2; ++j) {
                    MMAF16(acc[msub][2 * j],     a[msub], bfr[j][0], bfr[j][1]);
                    MMAF16(acc[msub][2 * j + 1], a[msub], bfr[j][2], bfr[j][3]);
                }
        }
    }

    const int r = lane >> 2, cpair = (lane & 3) * 2;
    #pragma unroll
    for (int msub = 0; msub < 2; ++msub) {
        const int gm0 = m0 + warp_m * 32 + msub * 16 + r;
        #pragma unroll
        for (int j = 0; j < 4; ++j) {
            const int ln = warp_n * 32 + j * 8 + cpair;
            const int gn = ntile * 128 + ln;
            const float bb0 = s_bias[ln], bb1 = s_bias[ln + 1];
            __half2 v0 = __floats2half2_rn(fmaxf(acc[msub][j][0] + bb0, 0.f),
                                           fmaxf(acc[msub][j][1] + bb1, 0.f));
            __half2 v1 = __floats2half2_rn(fmaxf(acc[msub][j][2] + bb0, 0.f),
                                           fmaxf(acc[msub][j][3] + bb1, 0.f));
            *(__half2*)&g_xh[(size_t)gm0 * C1 + gn] = v0;
            *(__half2*)&g_xh[(size_t)(gm0 + 8) * C1 + gn] = v1;
        }
    }
}

// ---------------- implicit fp16 GEMM: 64x128 tile, 256 thr, 2 CTA/SM, 2-stage ----------------
#define STG 24576
#define GEMM_SMEM (1024 + 2 * STG)

__global__ void __launch_bounds__(256, 2) gemm_kernel(const float* __restrict__ bias) {
    extern __shared__ char sm[];
    float* s_bias = (float*)sm;
    const uint32_t smb = smem_u32(sm);
    const int tid = threadIdx.x, lane = tid & 31, wid = tid >> 5;
    const int mtile = blockIdx.x, ntile = blockIdx.y;
    if (tid < 128) s_bias[tid] = bias[ntile * 128 + tid];

    const char* Bh = (const char*)g_Bh + (size_t)ntile * 128 * (KTOT * 2);

    int abase[2], aso2[2];
    #pragma unroll
    for (int i = 0; i < 2; ++i) {
        const int lin = tid + i * 256;
        const int ar = lin >> 3, ch = lin & 7;
        const int m = mtile * 64 + ar;
        const int bb = m / 36, sp = m - bb * 36;
        const int pbase = (2 * (sp / 6)) * 20 + 2 * (sp % 6);
        abase[i] = ((bb * 400 + pbase) << 8) + ch * 8;
        aso2[i] = ar * 128 + ((ch ^ (ar & 7)) << 4);
    }
    int brow[4], bso[4], bch[4];
    #pragma unroll
    for (int i = 0; i < 4; ++i) {
        int lin = tid + i * 256;
        brow[i] = lin >> 3; bch[i] = lin & 7;
        bso[i] = brow[i] * 128 + ((bch[i] ^ (brow[i] & 7)) << 4);
    }

    const int warp_m = wid >> 2, warp_n = wid & 3;
    int a_off[2], a_sw[2];
    #pragma unroll
    for (int sub = 0; sub < 2; ++sub) {
        int row = warp_m * 32 + sub * 16 + (lane & 15);
        a_off[sub] = row * 128; a_sw[sub] = row & 7;
    }
    const int a_cb = lane >> 4;
    int b_off[2], b_sw[2];
    #pragma unroll
    for (int j = 0; j < 2; ++j) {
        int row = warp_n * 32 + j * 16 + ((lane >> 4) << 3) + (lane & 7);
        b_off[j] = row * 128; b_sw[j] = row & 7;
    }
    const int b_cb = (lane >> 3) & 1;

    float acc[2][4][4];
    #pragma unroll
    for (int m = 0; m < 2; ++m)
        #pragma unroll
        for (int j = 0; j < 4; ++j)
            #pragma unroll
            for (int q = 0; q < 4; ++q) acc[m][j][q] = 0.f;

    auto issue = [&](int kk, int buf) {
        const uint32_t sA = smb + 1024 + buf * STG;
        const uint32_t sB = sA + 8192;
        const int r = kk >> 2, icq = kk & 3;
        const int dy = (r * 57) >> 9;
        const int poff = ((dy * 20 + (r - dy * 9)) << 8) + (icq << 6);
        #pragma unroll
        for (int i = 0; i < 2; ++i) {
            const size_t e = (size_t)(abase[i] + poff) * 2;
            CP_ASYNC16(sA + aso2[i], (const char*)g_xh + e);
        }
        const size_t kbyte = (size_t)kk * 128;
        #pragma unroll
        for (int i = 0; i < 4; ++i) {
            const size_t go = (size_t)brow[i] * (KTOT * 2) + kbyte + bch[i] * 16;
            CP_ASYNC16(sB + bso[i], Bh + go);
        }
        CP_COMMIT();
    };

    issue(0, 0);
    for (int t = 0; t < NKT; ++t) {
        if (t + 1 < NKT) issue(t + 1, (t + 1) & 1);
        else CP_COMMIT();
        CP_WAIT1();
        __syncthreads();
        const uint32_t sA = smb + 1024 + (t & 1) * STG;
        const uint32_t sB = sA + 8192;
        #pragma unroll
        for (int ks = 0; ks < 4; ++ks) {
            uint32_t a[2][4], bfr[2][4];
            #pragma unroll
            for (int sub = 0; sub < 2; ++sub) {
                uint32_t co = ((((ks << 1) + a_cb) ^ a_sw[sub]) << 4);
                LDMX4(a[sub][0], a[sub][1], a[sub][2], a[sub][3], sA + a_off[sub] + co);
            }
            #pragma unroll
            for (int j = 0; j < 2; ++j) {
                uint32_t co = ((((ks << 1) + b_cb) ^ b_sw[j]) << 4);
                LDMX4(bfr[j][0], bfr[j][1], bfr[j][2], bfr[j][3], sB + b_off[j] + co);
            }
            #pragma unroll
            for (int msub = 0; msub < 2; ++msub)
                #pragma unroll
                for (int j = 0; j < 2; ++j) {
                    MMAF16(acc[msub][2 * j],     a[msub], bfr[j][0], bfr[j][1]);
                    MMAF16(acc[msub][2 * j + 1], a[msub], bfr[j][2], bfr[j][3]);
                }
        }
        __syncthreads();
    }
    CP_WAIT0();

    const int r = lane >> 2, cpair = (lane & 3) * 2;
    #pragma unroll
    for (int msub = 0; msub < 2; ++msub) {
        const int gm0 = mtile * 64 + warp_m * 32 + msub * 16 + r;
        #pragma unroll
        for (int j = 0; j < 4; ++j) {
            const int ln = warp_n * 32 + j * 8 + cpair;
            const int gn = ntile * 128 + ln;
            const float b0 = s_bias[ln], b1 = s_bias[ln + 1];
            float2 v0 = {acc[msub][j][0] + b0, acc[msub][j][1] + b1};
            float2 v1 = {acc[msub][j][2] + b0, acc[msub][j][3] + b1};
            *(float2*)&g_pc[(size_t)gm0 * C1 + gn] = v0;
            *(float2*)&g_pc[(size_t)(gm0 + 8) * C1 + gn] = v1;
        }
    }
}

// ---------------- squash ----------------
__global__ void squash_u_kernel() {
    __shared__ float s[8][256];
    const int tid = threadIdx.x, w = tid >> 5, l = tid & 31;
    const int m = blockIdx.x * 8 + w;
    const float* row = g_pc + (size_t)m * C1;
    float4 r0 = ((const float4*)row)[l * 2];
    float4 r1 = ((const float4*)row)[l * 2 + 1];
    *(float4*)&s[w][l * 8]     = r0;
    *(float4*)&s[w][l * 8 + 4] = r1;
    __syncwarp();
    float v[PCD];
    float sq = 0.f;
    #pragma unroll
    for (int d = 0; d < PCD; ++d) {
        v[d] = s[w][d * 32 + l];
        sq += v[d] * v[d];
    }
    const float sc = sq / (1.f + sq) / sqrtf(sq + 1e-7f);
    const int b = m / 36, sp = m % 36;
    const int n = l * 36 + sp;
    float4 o0 = {v[0] * sc, v[1] * sc, v[2] * sc, v[3] * sc};
    float4 o1 = {v[4] * sc, v[5] * sc, v[6] * sc, v[7] * sc};
    float* dst = g_u + ((size_t)n * BATCH + b) * PCD;
    *(float4*)dst = o0;
    *(float4*)(dst + 4) = o1;
}

// ---------------- u_hat -> fp16 ----------------
__global__ void wu_kernel(const float* __restrict__ W) {
    __shared__ float s_u[64 * PCD];
    const int n = blockIdx.x;
    const int t = threadIdx.x;
    float wr[PCD];
    #pragma unroll
    for (int p = 0; p < PCD; ++p) wr[p] = W[n * (NC * DCD * PCD) + t * PCD + p];
    for (int b0 = 0; b0 < BATCH; b0 += 64) {
        __syncthreads();
        const uint4* src = (const uint4*)(g_u + ((size_t)n * BATCH + b0) * PCD);
        for (int i = t; i < 128; i += 160) ((uint4*)s_u)[i] = src[i];
        __syncthreads();
        for (int bb = 0; bb < 64; ++bb) {
            const float* up = &s_u[bb * PCD];
            float dot = 0.f;
            #pragma unroll
            for (int p = 0; p < PCD; ++p) dot += wr[p] * up[p];
            g_WUh[((size_t)((b0 + bb) * NPRIM + n)) * 160 + t] = __float2half_rn(dot);
        }
    }
}

// ---------------- dynamic routing: 20 warps (640 thr), warp-per-n stride 20 ----------------
#define NWARP 20
#define ROUT_SMEM ((11520 + NWARP * 160 + 160 + 16) * 4)

__device__ __forceinline__ void rout_reduce_squash(
    float* s_red, float* s_v, float* s_scale, const float* acc,
    int tid, int w, int l, float cs) {
    #pragma unroll
    for (int j = 0; j < 5; ++j) s_red[w * 160 + 32 * j + l] = acc[j];
    __syncthreads();
    if (tid < 160) {
        float v = 0.f;
        #pragma unroll
        for (int ww = 0; ww < NWARP; ++ww) v += s_red[ww * 160 + tid];
        s_v[tid] = v * cs;
    }
    __syncthreads();
    if (tid < NC) {
        float sq = 0.f;
        #pragma unroll
        for (int d = 0; d < DCD; ++d) { float x = s_v[tid * DCD + d]; sq += x * x; }
        s_scale[tid] = sq / (1.f + sq) / sqrtf(sq + 1e-7f);
    }
    __syncthreads();
    if (tid < 160) s_v[tid] *= s_scale[tid >> 4];
    __syncthreads();
}

__global__ void routing_kernel(float* __restrict__ out) {
    extern __shared__ float smf[];
    float* s_b     = smf;
    float* s_red   = smf + 11520;
    float* s_v     = smf + 11520 + NWARP * 160;
    float* s_scale = s_v + 160;
    const int b = blockIdx.x, tid = threadIdx.x;
    const int w = tid >> 5, l = tid & 31;
    const int myh = l >> 4;
    const size_t wub = (size_t)b * NPRIM * 160;
    const unsigned FULL = 0xffffffffu;
    float acc[5];

    #pragma unroll
    for (int j = 0; j < 5; ++j) acc[j] = 0.f;
    for (int n = w; n < NPRIM; n += NWARP) {
        const __half* row = g_WUh + wub + (size_t)n * 160;
        #pragma unroll
        for (int j = 0; j < 5; ++j) acc[j] += __half2float(row[l + 32 * j]);
    }
    rout_reduce_squash(s_red, s_v, s_scale, acc, tid, w, l, 0.1f);

    #pragma unroll
    for (int j = 0; j < 5; ++j) acc[j] = 0.f;
    for (int n = w; n < NPRIM; n += NWARP) {
        const __half* row = g_WUh + wub + (size_t)n * 160;
        float wv[5], t[5];
        #pragma unroll
        for (int j = 0; j < 5; ++j) wv[j] = __half2float(row[l + 32 * j]);
        #pragma unroll
        for (int j = 0; j < 5; ++j) t[j] = s_v[l + 32 * j] * wv[j];
        #pragma unroll
        for (int j = 0; j < 5; ++j) {
            t[j] += __shfl_xor_sync(FULL, t[j], 8);
            t[j] += __shfl_xor_sync(FULL, t[j], 4);
            t[j] += __shfl_xor_sync(FULL, t[j], 2);
            t[j] += __shfl_xor_sync(FULL, t[j], 1);
            t[j] *= 0.1f;
        }
        float o[5];
        #pragma unroll
        for (int j = 0; j < 5; ++j) o[j] = __shfl_xor_sync(FULL, t[j], 16);
        float selt = t[0], selo = o[0];
        #pragma unroll
        for (int jj = 1; jj < 5; ++jj) {
            bool p = ((l >> 1) == jj);
            selt = p ? t[jj] : selt;
            selo = p ? o[jj] : selo;
        }
        const float bv = (l & 1) ? selo : selt;
        if (l < NC) s_b[n * NC + l] = bv;
        float m = (l < NC) ? bv : -1e30f;
        m = fmaxf(m, __shfl_xor_sync(FULL, m, 16));
        m = fmaxf(m, __shfl_xor_sync(FULL, m, 8));
        m = fmaxf(m, __shfl_xor_sync(FULL, m, 4));
        m = fmaxf(m, __shfl_xor_sync(FULL, m, 2));
        m = fmaxf(m, __shfl_xor_sync(FULL, m, 1));
        float e = (l < NC) ? __expf(bv - m) : 0.f;
        float S = e;
        S += __shfl_xor_sync(FULL, S, 16);
        S += __shfl_xor_sync(FULL, S, 8);
        S += __shfl_xor_sync(FULL, S, 4);
        S += __shfl_xor_sync(FULL, S, 2);
        S += __shfl_xor_sync(FULL, S, 1);
        const float en = e / S;
        #pragma unroll
        for (int j = 0; j < 5; ++j) {
            float cf = __shfl_sync(FULL, en, 2 * j + myh);
            acc[j] += cf * wv[j];
        }
    }
    rout_reduce_squash(s_red, s_v, s_scale, acc, tid, w, l, 1.f);

    #pragma unroll
    for (int j = 0; j < 5; ++j) acc[j] = 0.f;
    for (int n = w; n < NPRIM; n += NWARP) {
        const __half* row = g_WUh + wub + (size_t)n * 160;
        float wv[5];
        #pragma unroll
        for (int j = 0; j < 5; ++j) wv[j] = __half2float(row[l + 32 * j]);
        const float bv1 = (l < NC) ? s_b[n * NC + l] : 0.f;
        float m1 = (l < NC) ? bv1 : -1e30f;
        m1 = fmaxf(m1, __shfl_xor_sync(FULL, m1, 16));
        m1 = fmaxf(m1, __shfl_xor_sync(FULL, m1, 8));
        m1 = fmaxf(m1, __shfl_xor_sync(FULL, m1, 4));
        m1 = fmaxf(m1, __shfl_xor_sync(FULL, m1, 2));
        m1 = fmaxf(m1, __shfl_xor_sync(FULL, m1, 1));
        float e1 = (l < NC) ? __expf(bv1 - m1) : 0.f;
        float S1 = e1;
        S1 += __shfl_xor_sync(FULL, S1, 16);
        S1 += __shfl_xor_sync(FULL, S1, 8);
        S1 += __shfl_xor_sync(FULL, S1, 4);
        S1 += __shfl_xor_sync(FULL, S1, 2);
        S1 += __shfl_xor_sync(FULL, S1, 1);
        const float en1 = e1 / S1;
        float t2[5];
        #pragma unroll
        for (int j = 0; j < 5; ++j) {
            float cf1 = __shfl_sync(FULL, en1, 2 * j + myh);
            t2[j] = s_v[l + 32 * j] * cf1 * wv[j];
            t2[j] += __shfl_xor_sync(FULL, t2[j], 8);
            t2[j] += __shfl_xor_sync(FULL, t2[j], 4);
            t2[j] += __shfl_xor_sync(FULL, t2[j], 2);
            t2[j] += __shfl_xor_sync(FULL, t2[j], 1);
        }
        float o2[5];
        #pragma unroll
        for (int j = 0; j < 5; ++j) o2[j] = __shfl_xor_sync(FULL, t2[j], 16);
        float selt = t2[0], selo = o2[0];
        #pragma unroll
        for (int jj = 1; jj < 5; ++jj) {
            bool p = ((l >> 1) == jj);
            selt = p ? t2[jj] : selt;
            selo = p ? o2[jj] : selo;
        }
        const float b2v = bv1 + ((l & 1) ? selo : selt);
        float m2 = (l < NC) ? b2v : -1e30f;
        m2 = fmaxf(m2, __shfl_xor_sync(FULL, m2, 16));
        m2 = fmaxf(m2, __shfl_xor_sync(FULL, m2, 8));
        m2 = fmaxf(m2, __shfl_xor_sync(FULL, m2, 4));
        m2 = fmaxf(m2, __shfl_xor_sync(FULL, m2, 2));
        m2 = fmaxf(m2, __shfl_xor_sync(FULL, m2, 1));
        float e2 = (l < NC) ? __expf(b2v - m2) : 0.f;
        float S2 = e2;
        S2 += __shfl_xor_sync(FULL, S2, 16);
        S2 += __shfl_xor_sync(FULL, S2, 8);
        S2 += __shfl_xor_sync(FULL, S2, 4);
        S2 += __shfl_xor_sync(FULL, S2, 2);
        S2 += __shfl_xor_sync(FULL, S2, 1);
        const float en2 = e2 / S2;
        #pragma unroll
        for (int j = 0; j < 5; ++j) {
            float cf2 = __shfl_sync(FULL, en2, 2 * j + myh);
            acc[j] += cf2 * wv[j];
        }
    }
    rout_reduce_squash(s_red, s_v, s_scale, acc, tid, w, l, 1.f);

    if (tid < 160) g_v[b * 160 + tid] = s_v[tid];
    if (tid < NC) {
        float sq = 0.f;
        #pragma unroll
        for (int d = 0; d < DCD; ++d) { float x = s_v[tid * DCD + d]; sq += x * x; }
        out[b * NC + tid] = sqrtf(sq);
    }
}

// ---------------- masked decoder: 2 images per block, 512 threads, fp16 weights ----------------
__global__ void decoder_kernel(const int* __restrict__ labels,
                               const float* __restrict__ w1, const float* __restrict__ bb1,
                               const float* __restrict__ bb2,
                               const float* __restrict__ bb3,
                               float* __restrict__ out) {
    __shared__ float h0[2][DCD];
    __shared__ float h1[2][512];
    __shared__ float h2[2][1024];
    __shared__ int   lab[2];
    const int t = threadIdx.x;   // 0..511
    const int b0 = blockIdx.x * 2;
    if (t < 2) lab[t] = labels[b0 + t];
    __syncthreads();
    if (t < 32) {
        int i = t >> 4, d = t & 15;
        h0[i][d] = g_v[(b0 + i) * 160 + lab[i] * DCD + d];
    }
    __syncthreads();
    for (int j = t; j < 512; j += 512) {
        float a[2];
        #pragma unroll
        for (int i = 0; i < 2; ++i) a[i] = bb1[j];
        #pragma unroll
        for (int k = 0; k < DCD; ++k) {
            #pragma unroll
            for (int i = 0; i < 2; ++i)
                a[i] += h0[i][k] * w1[(lab[i] * DCD + k) * 512 + j];
        }
        #pragma unroll
        for (int i = 0; i < 2; ++i) h1[i][j] = fmaxf(a[i], 0.f);
    }
    __syncthreads();
    for (int j = t; j < 1024; j += 512) {
        float a[2];
        #pragma unroll
        for (int i = 0; i < 2; ++i) a[i] = bb2[j];
        for (int k = 0; k < 512; ++k) {
            float wv = __half2float(g_w2h[k * 1024 + j]);
            #pragma unroll
            for (int i = 0; i < 2; ++i) a[i] += h1[i][k] * wv;
        }
        #pragma unroll
        for (int i = 0; i < 2; ++i) h2[i][j] = fmaxf(a[i], 0.f);
    }
    __syncthreads();
    for (int j = t; j < 784; j += 512) {
        float a[2];
        #pragma unroll
        for (int i = 0; i < 2; ++i) a[i] = bb3[j];
        for (int k = 0; k < 1024; ++k) {
            float wv = __half2float(g_w3h[k * 784 + j]);
            #pragma unroll
            for (int i = 0; i < 2; ++i) a[i] += h2[i][k] * wv;
        }
        #pragma unroll
        for (int i = 0; i < 2; ++i)
            out[BATCH * NC + (b0 + i) * 784 + j] = 1.f / (1.f + __expf(-a[i]));
    }
}

// ---------------- launch ----------------
extern "C" void kernel_launch(void* const* d_in, const int* in_sizes, int n_in,
                              void* d_out, int out_size) {
    const float* inputs  = (const float*)d_in[0];
    const int*   labels  = (const int*)d_in[1];
    const float* conv1_w = (const float*)d_in[2];
    const float* conv1_b = (const float*)d_in[3];
    const float* pc_w    = (const float*)d_in[4];
    const float* pc_b    = (const float*)d_in[5];
    const float* rw      = (const float*)d_in[6];
    const float* dw1     = (const float*)d_in[7];
    const float* db1     = (const float*)d_in[8];
    const float* dw2     = (const float*)d_in[9];
    const float* db2     = (const float*)d_in[10];
    const float* dw3     = (const float*)d_in[11];
    const float* db3     = (const float*)d_in[12];
    float* out = (float*)d_out;

    convert_c1w_kernel<<<256, 128>>>(conv1_w);
    convert_w_kernel<<<C1, 256>>>(pc_w);
    convert_dec_kernel<<<(1024 * 784 + 255) / 256, 256>>>(dw2, dw3);

    cudaFuncSetAttribute(conv1_gemm_kernel, cudaFuncAttributeMaxDynamicSharedMemorySize, C1_SMEM);
    conv1_gemm_kernel<<<dim3(800, 2), 512, C1_SMEM>>>(inputs, conv1_b);

    cudaFuncSetAttribute(gemm_kernel, cudaFuncAttributeMaxDynamicSharedMemorySize, GEMM_SMEM);
    gemm_kernel<<<dim3(144, 2), 256, GEMM_SMEM>>>(pc_b);

    squash_u_kernel<<<NPRIM, 256>>>();
    wu_kernel<<<NPRIM, 160>>>(rw);

    cudaFuncSetAttribute(routing_kernel, cudaFuncAttributeMaxDynamicSharedMemorySize, ROUT_SMEM);
    routing_kernel<<<BATCH, 32 * NWARP, ROUT_SMEM>>>(out);

    decoder_kernel<<<BATCH / 2, 512>>>(labels, dw1, db1, db2, db3, out);
}